// round 1
// baseline (speedup 1.0000x reference)
#include <cuda_runtime.h>

#define N_NODES 20000
#define N_EDGES 320000
#define HID 256
#define NF (N_NODES * HID)

// ---------------- scratch (device globals; no allocation allowed) ----------
__device__ float g_deg[N_NODES];
__device__ float g_dinv[N_NODES];
__device__ float g_w[N_NODES];
__device__ float g_z[HID];
__device__ float g_bufA[NF];   // h (layer output)
__device__ float g_bufB[NF];   // xw (gemm output)
__device__ float g_bufC[NF];   // agg (scatter target)

// ---------------- degree / dinv --------------------------------------------
__global__ void k_deg(const int* __restrict__ dst) {
    int e = blockIdx.x * blockDim.x + threadIdx.x;
    if (e < N_EDGES) atomicAdd(&g_deg[dst[e]], 1.0f);
}

__global__ void k_dinv() {
    int n = blockIdx.x * blockDim.x + threadIdx.x;
    if (n < N_NODES) g_dinv[n] = rsqrtf(g_deg[n] + 1.0f);
}

// ---------------- fp32 tiled GEMM: C[M,256] = A[M,256] @ W[256,256] --------
// BM=BN=64, BK=16, 256 threads, 4x4 micro-tile per thread.
__global__ __launch_bounds__(256) void k_gemm(const float* __restrict__ A,
                                              const float* __restrict__ W,
                                              float* __restrict__ C) {
    __shared__ float As[16][65];  // padded: transposed A tile As[k][row]
    __shared__ float Bs[16][68];  // padded (float4-aligned): Bs[k][col]

    const int tid = threadIdx.x;
    const int tx = tid & 15;      // 0..15 -> col group
    const int ty = tid >> 4;      // 0..15 -> row group
    const int row0 = blockIdx.y * 64;
    const int col0 = blockIdx.x * 64;

    // load mapping
    const int a_row = tid >> 2;            // 0..63
    const int a_k4  = (tid & 3) * 4;       // 0,4,8,12
    const int b_k   = tid >> 4;            // 0..15
    const int b_c4  = (tid & 15) * 4;      // 0..60

    float acc[4][4] = {};

    for (int kt = 0; kt < 256; kt += 16) {
        float4 av = make_float4(0.f, 0.f, 0.f, 0.f);
        int gr = row0 + a_row;
        if (gr < N_NODES)
            av = *(const float4*)(A + (long)gr * 256 + kt + a_k4);
        As[a_k4 + 0][a_row] = av.x;
        As[a_k4 + 1][a_row] = av.y;
        As[a_k4 + 2][a_row] = av.z;
        As[a_k4 + 3][a_row] = av.w;

        float4 bv = *(const float4*)(W + (long)(kt + b_k) * 256 + col0 + b_c4);
        *(float4*)&Bs[b_k][b_c4] = bv;

        __syncthreads();

#pragma unroll
        for (int k = 0; k < 16; k++) {
            float a[4], b[4];
#pragma unroll
            for (int u = 0; u < 4; u++) a[u] = As[k][ty * 4 + u];
#pragma unroll
            for (int v = 0; v < 4; v++) b[v] = Bs[k][tx * 4 + v];
#pragma unroll
            for (int u = 0; u < 4; u++)
#pragma unroll
                for (int v = 0; v < 4; v++)
                    acc[u][v] = fmaf(a[u], b[v], acc[u][v]);
        }
        __syncthreads();
    }

#pragma unroll
    for (int u = 0; u < 4; u++) {
        int gr = row0 + ty * 4 + u;
        if (gr < N_NODES) {
            float4 o = make_float4(acc[u][0], acc[u][1], acc[u][2], acc[u][3]);
            *(float4*)(C + (long)gr * 256 + col0 + tx * 4) = o;
        }
    }
}

// ---------------- edge aggregation: agg[dst] += coef * xw[src] -------------
// 64 threads per edge, each handles a float4 chunk (scalar atomics for now).
__global__ __launch_bounds__(256) void k_edge_agg(const int* __restrict__ src,
                                                  const int* __restrict__ dst,
                                                  const float* __restrict__ xw,
                                                  float* __restrict__ agg) {
    unsigned gid = blockIdx.x * 256u + threadIdx.x;
    unsigned e = gid >> 6;
    unsigned ch = gid & 63u;
    if (e >= N_EDGES) return;
    int s = src[e], d = dst[e];
    float coef = __ldg(&g_dinv[s]) * __ldg(&g_dinv[d]);
    float4 v = *(const float4*)(xw + (long)s * 256 + ch * 4);
    float* a = agg + (long)d * 256 + ch * 4;
    atomicAdd(a + 0, v.x * coef);
    atomicAdd(a + 1, v.y * coef);
    atomicAdd(a + 2, v.z * coef);
    atomicAdd(a + 3, v.w * coef);
}

// ---------------- epilogue: out = relu(agg + xw*dinv^2 + b) ---------------
__global__ void k_epi(const float* __restrict__ agg, const float* __restrict__ xw,
                      const float* __restrict__ bias, float* __restrict__ out) {
    int i = blockIdx.x * blockDim.x + threadIdx.x;
    if (i >= NF) return;
    int n = i >> 8;
    int c = i & 255;
    float di = g_dinv[n];
    float v = agg[i] + xw[i] * di * di + bias[c];
    out[i] = fmaxf(v, 0.f);
}

// ---------------- collapsed layer 3 -----------------------------------------
__global__ void k_wedge(const int* __restrict__ src, const int* __restrict__ dst) {
    int e = blockIdx.x * blockDim.x + threadIdx.x;
    if (e < N_EDGES) {
        int s = src[e], d = dst[e];
        atomicAdd(&g_w[s], g_dinv[s] * g_dinv[d]);
    }
}

__global__ void k_wself() {
    int n = blockIdx.x * blockDim.x + threadIdx.x;
    if (n < N_NODES) {
        float di = g_dinv[n];
        g_w[n] += di * di;
    }
}

// z[c] += sum_n w[n] * h[n][c]   (accumulated across both branches)
__global__ __launch_bounds__(256) void k_zred(const float* __restrict__ h) {
    int c = threadIdx.x;
    float local = 0.f;
    for (int n = blockIdx.x; n < N_NODES; n += gridDim.x)
        local += __ldg(&g_w[n]) * h[(long)n * 256 + c];
    atomicAdd(&g_z[c], local);
}

// pooled = (z @ W3)/(2N) + b3 ; out = pooled @ Wl + bl
__global__ void k_final(const float* __restrict__ W3, const float* __restrict__ b3,
                        const float* __restrict__ Wl, const float* __restrict__ bl,
                        float* __restrict__ out) {
    int j = threadIdx.x;  // 256 threads
    __shared__ float sz[HID];
    __shared__ float so[8];
    sz[j] = g_z[j];
    if (j < 8) so[j] = 0.f;
    __syncthreads();

    float acc = 0.f;
#pragma unroll 8
    for (int k = 0; k < HID; k++)
        acc = fmaf(sz[k], W3[k * HID + j], acc);
    float pv = acc * (1.0f / (2.0f * N_NODES)) + b3[j];

#pragma unroll
    for (int c = 0; c < 5; c++)
        atomicAdd(&so[c], pv * Wl[j * 5 + c]);
    __syncthreads();
    if (j < 5) out[j] = so[j] + bl[j];
}

// ---------------------------------------------------------------------------
extern "C" void kernel_launch(void* const* d_in, const int* in_sizes, int n_in,
                              void* d_out, int out_size) {
    const float* x1 = (const float*)d_in[0];
    const int*   ei1 = (const int*)d_in[1];
    const float* x2 = (const float*)d_in[2];
    const int*   ei2 = (const int*)d_in[3];
    const float* W1 = (const float*)d_in[4];
    const float* b1 = (const float*)d_in[5];
    const float* W2 = (const float*)d_in[6];
    const float* b2 = (const float*)d_in[7];
    const float* W3 = (const float*)d_in[8];
    const float* b3 = (const float*)d_in[9];
    const float* Wl = (const float*)d_in[10];
    const float* bl = (const float*)d_in[11];
    float* out = (float*)d_out;

    float *deg, *w, *z, *A, *B, *C;
    cudaGetSymbolAddress((void**)&deg, g_deg);
    cudaGetSymbolAddress((void**)&w,   g_w);
    cudaGetSymbolAddress((void**)&z,   g_z);
    cudaGetSymbolAddress((void**)&A,   g_bufA);
    cudaGetSymbolAddress((void**)&B,   g_bufB);
    cudaGetSymbolAddress((void**)&C,   g_bufC);

    const dim3 gemm_grid(4, (N_NODES + 63) / 64);
    const int edge_blocks = (N_EDGES + 255) / 256;
    const int node_blocks = (N_NODES + 255) / 256;
    const int agg_blocks  = (N_EDGES * 64) / 256;   // 80000
    const int nf_blocks   = (NF + 255) / 256;

    cudaMemsetAsync(z, 0, HID * sizeof(float));

    for (int br = 0; br < 2; br++) {
        const float* x  = br == 0 ? x1 : x2;
        const int*   ei = br == 0 ? ei1 : ei2;
        const int* src = ei;
        const int* dst = ei + N_EDGES;

        cudaMemsetAsync(deg, 0, N_NODES * sizeof(float));
        k_deg<<<edge_blocks, 256>>>(dst);
        k_dinv<<<node_blocks, 256>>>();

        // layer 1: h1 = relu(agg(x@W1) + b1)
        k_gemm<<<gemm_grid, 256>>>(x, W1, B);
        cudaMemsetAsync(C, 0, NF * sizeof(float));
        k_edge_agg<<<agg_blocks, 256>>>(src, dst, B, C);
        k_epi<<<nf_blocks, 256>>>(C, B, b1, A);

        // layer 2: h2 = relu(agg(h1@W2) + b2)
        k_gemm<<<gemm_grid, 256>>>(A, W2, B);
        cudaMemsetAsync(C, 0, NF * sizeof(float));
        k_edge_agg<<<agg_blocks, 256>>>(src, dst, B, C);
        k_epi<<<nf_blocks, 256>>>(C, B, b2, A);

        // layer 3 collapsed: z += sum_n w[n] * h2[n]
        cudaMemsetAsync(w, 0, N_NODES * sizeof(float));
        k_wedge<<<edge_blocks, 256>>>(src, dst);
        k_wself<<<node_blocks, 256>>>();
        k_zred<<<256, 256>>>(A);
    }

    k_final<<<1, 256>>>(W3, b3, Wl, bl, out);
}

// round 2
// speedup vs baseline: 1.6367x; 1.6367x over previous
#include <cuda_runtime.h>

#define N_NODES 20000
#define N_EDGES 320000
#define HID 256
#define NF (N_NODES * HID)

// ---------------- scratch (device globals; no allocation allowed) ----------
__device__ float g_deg[N_NODES];
__device__ float g_dinv[N_NODES];
__device__ float g_w[N_NODES];
__device__ float g_z[HID];
__device__ float g_bufB[NF];   // xw (gemm output)
__device__ float g_bufC[NF];   // agg (scatter target / layer pre-relu output)

// ---------------- vector reduction helper ----------------------------------
__device__ __forceinline__ void red_add_v4(float* addr, float x, float y, float z, float w) {
    asm volatile("red.global.add.v4.f32 [%0], {%1, %2, %3, %4};"
                 :: "l"(addr), "f"(x), "f"(y), "f"(z), "f"(w) : "memory");
}

// ---------------- degree / dinv --------------------------------------------
__global__ void k_deg(const int* __restrict__ dst) {
    int e = blockIdx.x * blockDim.x + threadIdx.x;
    if (e < N_EDGES) atomicAdd(&g_deg[dst[e]], 1.0f);
}

__global__ void k_dinv() {
    int n = blockIdx.x * blockDim.x + threadIdx.x;
    if (n < N_NODES) g_dinv[n] = rsqrtf(g_deg[n] + 1.0f);
}

// ---------------- fp32 tiled GEMM: C[M,256] = act(A)[M,256] @ W[256,256] ----
// BM=128, BN=64, BK=16, 256 threads, 8x4 micro-tile per thread.
// RELU: apply relu to A elements on load (fuses previous layer's activation).
template <bool RELU>
__global__ __launch_bounds__(256) void k_gemm(const float* __restrict__ A,
                                              const float* __restrict__ W,
                                              float* __restrict__ C) {
    __shared__ float As[16][136];  // transposed A tile: As[k][row], padded
    __shared__ float Bs[16][68];   // Bs[k][col], padded (16B-aligned rows)

    const int tid = threadIdx.x;
    const int tx = tid & 15;       // col group (4 cols)
    const int ty = tid >> 4;       // row group (8 rows)
    const int row0 = blockIdx.y * 128;
    const int col0 = blockIdx.x * 64;

    // load mapping
    const int a_row = tid >> 1;          // 0..127
    const int a_k8  = (tid & 1) * 8;     // 0 or 8
    const int b_k   = tid >> 4;          // 0..15
    const int b_c4  = (tid & 15) * 4;    // 0..60

    float acc[8][4] = {};

    for (int kt = 0; kt < 256; kt += 16) {
        const int gr = row0 + a_row;
#pragma unroll
        for (int h = 0; h < 2; h++) {
            float4 av = make_float4(0.f, 0.f, 0.f, 0.f);
            if (gr < N_NODES) {
                av = *(const float4*)(A + (long)gr * 256 + kt + a_k8 + h * 4);
                if (RELU) {
                    av.x = fmaxf(av.x, 0.f); av.y = fmaxf(av.y, 0.f);
                    av.z = fmaxf(av.z, 0.f); av.w = fmaxf(av.w, 0.f);
                }
            }
            As[a_k8 + h * 4 + 0][a_row] = av.x;
            As[a_k8 + h * 4 + 1][a_row] = av.y;
            As[a_k8 + h * 4 + 2][a_row] = av.z;
            As[a_k8 + h * 4 + 3][a_row] = av.w;
        }
        {
            float4 bv = *(const float4*)(W + (long)(kt + b_k) * 256 + col0 + b_c4);
            *(float4*)&Bs[b_k][b_c4] = bv;
        }
        __syncthreads();

#pragma unroll
        for (int k = 0; k < 16; k++) {
            float a[8], b[4];
#pragma unroll
            for (int u = 0; u < 8; u++) a[u] = As[k][ty * 8 + u];
#pragma unroll
            for (int v = 0; v < 4; v++) b[v] = Bs[k][tx * 4 + v];
#pragma unroll
            for (int u = 0; u < 8; u++)
#pragma unroll
                for (int v = 0; v < 4; v++)
                    acc[u][v] = fmaf(a[u], b[v], acc[u][v]);
        }
        __syncthreads();
    }

#pragma unroll
    for (int u = 0; u < 8; u++) {
        const int gr = row0 + ty * 8 + u;
        if (gr < N_NODES) {
            float4 o = make_float4(acc[u][0], acc[u][1], acc[u][2], acc[u][3]);
            *(float4*)(C + (long)gr * 256 + col0 + tx * 4) = o;
        }
    }
}

// ---------------- init scatter target: C = xw*dinv^2 + bias ----------------
__global__ void k_init(const float* __restrict__ xw, const float* __restrict__ bias,
                       float* __restrict__ C) {
    int i = blockIdx.x * blockDim.x + threadIdx.x;
    if (i >= NF) return;
    int n = i >> 8;
    int c = i & 255;
    float di = g_dinv[n];
    C[i] = xw[i] * di * di + bias[c];
}

// ---------------- edge aggregation: C[dst] += coef * xw[src] ---------------
// 64 threads per edge, each handles one float4 chunk via red.global.v4.
__global__ __launch_bounds__(256) void k_edge_agg(const int* __restrict__ src,
                                                  const int* __restrict__ dst,
                                                  const float* __restrict__ xw,
                                                  float* __restrict__ agg) {
    unsigned gid = blockIdx.x * 256u + threadIdx.x;
    unsigned e = gid >> 6;
    unsigned ch = gid & 63u;
    if (e >= N_EDGES) return;
    int s = src[e], d = dst[e];
    float coef = __ldg(&g_dinv[s]) * __ldg(&g_dinv[d]);
    float4 v = *(const float4*)(xw + (long)s * 256 + ch * 4);
    float* a = agg + (long)d * 256 + ch * 4;
    red_add_v4(a, v.x * coef, v.y * coef, v.z * coef, v.w * coef);
}

// ---------------- collapsed layer 3 ----------------------------------------
__global__ void k_wedge(const int* __restrict__ src, const int* __restrict__ dst) {
    int e = blockIdx.x * blockDim.x + threadIdx.x;
    if (e < N_EDGES) {
        int s = src[e], d = dst[e];
        atomicAdd(&g_w[s], g_dinv[s] * g_dinv[d]);
    }
}

__global__ void k_wself() {
    int n = blockIdx.x * blockDim.x + threadIdx.x;
    if (n < N_NODES) {
        float di = g_dinv[n];
        g_w[n] += di * di;
    }
}

// z[c] += sum_n w[n] * relu(h[n][c])   (accumulated across both branches)
__global__ __launch_bounds__(256) void k_zred(const float* __restrict__ h) {
    int c = threadIdx.x;
    float local = 0.f;
    for (int n = blockIdx.x; n < N_NODES; n += gridDim.x)
        local += __ldg(&g_w[n]) * fmaxf(h[(long)n * 256 + c], 0.f);
    atomicAdd(&g_z[c], local);
}

// pooled = (z @ W3)/(2N) + b3 ; out = pooled @ Wl + bl
__global__ void k_final(const float* __restrict__ W3, const float* __restrict__ b3,
                        const float* __restrict__ Wl, const float* __restrict__ bl,
                        float* __restrict__ out) {
    int j = threadIdx.x;  // 256 threads
    __shared__ float sz[HID];
    __shared__ float so[8];
    sz[j] = g_z[j];
    if (j < 8) so[j] = 0.f;
    __syncthreads();

    float acc = 0.f;
#pragma unroll 8
    for (int k = 0; k < HID; k++)
        acc = fmaf(sz[k], W3[k * HID + j], acc);
    float pv = acc * (1.0f / (2.0f * N_NODES)) + b3[j];

#pragma unroll
    for (int c = 0; c < 5; c++)
        atomicAdd(&so[c], pv * Wl[j * 5 + c]);
    __syncthreads();
    if (j < 5) out[j] = so[j] + bl[j];
}

// ---------------------------------------------------------------------------
extern "C" void kernel_launch(void* const* d_in, const int* in_sizes, int n_in,
                              void* d_out, int out_size) {
    const float* x1 = (const float*)d_in[0];
    const int*   ei1 = (const int*)d_in[1];
    const float* x2 = (const float*)d_in[2];
    const int*   ei2 = (const int*)d_in[3];
    const float* W1 = (const float*)d_in[4];
    const float* b1 = (const float*)d_in[5];
    const float* W2 = (const float*)d_in[6];
    const float* b2 = (const float*)d_in[7];
    const float* W3 = (const float*)d_in[8];
    const float* b3 = (const float*)d_in[9];
    const float* Wl = (const float*)d_in[10];
    const float* bl = (const float*)d_in[11];
    float* out = (float*)d_out;

    float *deg, *w, *z, *B, *C;
    cudaGetSymbolAddress((void**)&deg, g_deg);
    cudaGetSymbolAddress((void**)&w,   g_w);
    cudaGetSymbolAddress((void**)&z,   g_z);
    cudaGetSymbolAddress((void**)&B,   g_bufB);
    cudaGetSymbolAddress((void**)&C,   g_bufC);

    const dim3 gemm_grid(4, (N_NODES + 127) / 128);
    const int edge_blocks = (N_EDGES + 255) / 256;
    const int node_blocks = (N_NODES + 255) / 256;
    const int agg_blocks  = (N_EDGES * 64) / 256;   // 80000
    const int nf_blocks   = (NF + 255) / 256;

    cudaMemsetAsync(z, 0, HID * sizeof(float));

    for (int br = 0; br < 2; br++) {
        const float* x  = br == 0 ? x1 : x2;
        const int*   ei = br == 0 ? ei1 : ei2;
        const int* src = ei;
        const int* dst = ei + N_EDGES;

        cudaMemsetAsync(deg, 0, N_NODES * sizeof(float));
        k_deg<<<edge_blocks, 256>>>(dst);
        k_dinv<<<node_blocks, 256>>>();

        // layer 1: C = (x@W1 scattered) + self + b1   (pre-relu)
        k_gemm<false><<<gemm_grid, 256>>>(x, W1, B);
        k_init<<<nf_blocks, 256>>>(B, b1, C);
        k_edge_agg<<<agg_blocks, 256>>>(src, dst, B, C);

        // layer 2: relu fused into gemm load
        k_gemm<true><<<gemm_grid, 256>>>(C, W2, B);
        k_init<<<nf_blocks, 256>>>(B, b2, C);
        k_edge_agg<<<agg_blocks, 256>>>(src, dst, B, C);

        // layer 3 collapsed: z += sum_n w[n] * relu(C[n])
        cudaMemsetAsync(w, 0, N_NODES * sizeof(float));
        k_wedge<<<edge_blocks, 256>>>(src, dst);
        k_wself<<<node_blocks, 256>>>();
        k_zred<<<256, 256>>>(C);
    }

    k_final<<<1, 256>>>(W3, b3, Wl, bl, out);
}

// round 3
// speedup vs baseline: 1.8659x; 1.1400x over previous
#include <cuda_runtime.h>

#define N_NODES 20000
#define N_EDGES 320000
#define HID 256
#define NF (N_NODES * HID)

// ---------------- scratch (device globals; no allocation allowed) ----------
__device__ float g_deg[N_NODES];
__device__ float g_dinv[N_NODES];
__device__ float g_w[N_NODES];
__device__ float g_z[HID];
__device__ float g_bufB[NF];        // xw (gemm output)
__device__ float g_bufC[NF];        // layer pre-relu output
__device__ int   g_rowptr[N_NODES + 1];
__device__ int   g_cursor[N_NODES];
__device__ int   g_csr_src[N_EDGES];
__device__ float g_csr_coef[N_EDGES];

// ---------------- degree / dinv --------------------------------------------
__global__ void k_deg(const int* __restrict__ dst) {
    int e = blockIdx.x * blockDim.x + threadIdx.x;
    if (e < N_EDGES) atomicAdd(&g_deg[dst[e]], 1.0f);
}

__global__ void k_dinv() {
    int n = blockIdx.x * blockDim.x + threadIdx.x;
    if (n < N_NODES) g_dinv[n] = rsqrtf(g_deg[n] + 1.0f);
}

// ---------------- single-block exclusive scan of degrees -> rowptr ----------
__global__ __launch_bounds__(1024) void k_scan() {
    __shared__ int partial[1024];
    const int t = threadIdx.x;
    const int CH = 20;  // 1024*20 = 20480 >= 20000
    int local[CH];
    int base = t * CH;
    int s = 0;
#pragma unroll
    for (int i = 0; i < CH; i++) {
        int idx = base + i;
        int d = (idx < N_NODES) ? (int)g_deg[idx] : 0;
        local[i] = s;
        s += d;
    }
    partial[t] = s;
    __syncthreads();
    for (int off = 1; off < 1024; off <<= 1) {
        int v = (t >= off) ? partial[t - off] : 0;
        __syncthreads();
        partial[t] += v;
        __syncthreads();
    }
    int offset = (t > 0) ? partial[t - 1] : 0;
#pragma unroll
    for (int i = 0; i < CH; i++) {
        int idx = base + i;
        if (idx < N_NODES) {
            int v = offset + local[i];
            g_rowptr[idx] = v;
            g_cursor[idx] = v;
        }
    }
    if (t == 1023) g_rowptr[N_NODES] = partial[1023];
}

// ---------------- CSR fill (+ w[src] accumulation for collapsed layer 3) ---
__global__ void k_fill(const int* __restrict__ src, const int* __restrict__ dst) {
    int e = blockIdx.x * blockDim.x + threadIdx.x;
    if (e >= N_EDGES) return;
    int s = src[e], d = dst[e];
    float coef = g_dinv[s] * g_dinv[d];
    int pos = atomicAdd(&g_cursor[d], 1);
    g_csr_src[pos] = s;
    g_csr_coef[pos] = coef;
    atomicAdd(&g_w[s], coef);
}

__global__ void k_wself() {
    int n = blockIdx.x * blockDim.x + threadIdx.x;
    if (n < N_NODES) {
        float di = g_dinv[n];
        g_w[n] += di * di;
    }
}

// ---------------- fp32 tiled GEMM: C[M,256] = act(A)[M,256] @ W[256,256] ----
// BM=128, BN=64, BK=16, 256 threads, 8x4 micro-tile per thread.
template <bool RELU>
__global__ __launch_bounds__(256) void k_gemm(const float* __restrict__ A,
                                              const float* __restrict__ W,
                                              float* __restrict__ C) {
    __shared__ float As[16][136];
    __shared__ float Bs[16][68];

    const int tid = threadIdx.x;
    const int tx = tid & 15;
    const int ty = tid >> 4;
    const int row0 = blockIdx.y * 128;
    const int col0 = blockIdx.x * 64;

    const int a_row = tid >> 1;
    const int a_k8  = (tid & 1) * 8;
    const int b_k   = tid >> 4;
    const int b_c4  = (tid & 15) * 4;

    float acc[8][4] = {};

    for (int kt = 0; kt < 256; kt += 16) {
        const int gr = row0 + a_row;
#pragma unroll
        for (int h = 0; h < 2; h++) {
            float4 av = make_float4(0.f, 0.f, 0.f, 0.f);
            if (gr < N_NODES) {
                av = *(const float4*)(A + (long)gr * 256 + kt + a_k8 + h * 4);
                if (RELU) {
                    av.x = fmaxf(av.x, 0.f); av.y = fmaxf(av.y, 0.f);
                    av.z = fmaxf(av.z, 0.f); av.w = fmaxf(av.w, 0.f);
                }
            }
            As[a_k8 + h * 4 + 0][a_row] = av.x;
            As[a_k8 + h * 4 + 1][a_row] = av.y;
            As[a_k8 + h * 4 + 2][a_row] = av.z;
            As[a_k8 + h * 4 + 3][a_row] = av.w;
        }
        {
            float4 bv = *(const float4*)(W + (long)(kt + b_k) * 256 + col0 + b_c4);
            *(float4*)&Bs[b_k][b_c4] = bv;
        }
        __syncthreads();

#pragma unroll
        for (int k = 0; k < 16; k++) {
            float a[8], b[4];
#pragma unroll
            for (int u = 0; u < 8; u++) a[u] = As[k][ty * 8 + u];
#pragma unroll
            for (int v = 0; v < 4; v++) b[v] = Bs[k][tx * 4 + v];
#pragma unroll
            for (int u = 0; u < 8; u++)
#pragma unroll
                for (int v = 0; v < 4; v++)
                    acc[u][v] = fmaf(a[u], b[v], acc[u][v]);
        }
        __syncthreads();
    }

#pragma unroll
    for (int u = 0; u < 8; u++) {
        const int gr = row0 + ty * 8 + u;
        if (gr < N_NODES) {
            float4 o = make_float4(acc[u][0], acc[u][1], acc[u][2], acc[u][3]);
            *(float4*)(C + (long)gr * 256 + col0 + tx * 4) = o;
        }
    }
}

// ---------------- CSR gather aggregation ------------------------------------
// One block per dst node: C[n] = sum_e coef_e * xw[src_e] + xw[n]*dinv^2 + bias
__global__ __launch_bounds__(256) void k_gather(const float* __restrict__ xw,
                                                const float* __restrict__ bias,
                                                float* __restrict__ C) {
    const int n = blockIdx.x;
    const int c = threadIdx.x;
    const int beg = g_rowptr[n];
    const int end = g_rowptr[n + 1];
    const float di = g_dinv[n];

    float acc = fmaf(xw[(long)n * 256 + c], di * di, bias[c]);

    __shared__ int   ss[256];
    __shared__ float sc[256];

    for (int chunk = beg; chunk < end; chunk += 256) {
        const int m = min(256, end - chunk);
        if (c < m) {
            ss[c] = g_csr_src[chunk + c];
            sc[c] = g_csr_coef[chunk + c];
        }
        __syncthreads();

        float a0 = 0.f, a1 = 0.f, a2 = 0.f, a3 = 0.f;
        int i = 0;
        for (; i + 4 <= m; i += 4) {
            a0 = fmaf(sc[i + 0], xw[(long)ss[i + 0] * 256 + c], a0);
            a1 = fmaf(sc[i + 1], xw[(long)ss[i + 1] * 256 + c], a1);
            a2 = fmaf(sc[i + 2], xw[(long)ss[i + 2] * 256 + c], a2);
            a3 = fmaf(sc[i + 3], xw[(long)ss[i + 3] * 256 + c], a3);
        }
        for (; i < m; i++)
            a0 = fmaf(sc[i], xw[(long)ss[i] * 256 + c], a0);
        acc += (a0 + a1) + (a2 + a3);
        __syncthreads();
    }
    C[(long)n * 256 + c] = acc;
}

// z[c] += sum_n w[n] * relu(h[n][c])
__global__ __launch_bounds__(256) void k_zred(const float* __restrict__ h) {
    int c = threadIdx.x;
    float local = 0.f;
    for (int n = blockIdx.x; n < N_NODES; n += gridDim.x)
        local += __ldg(&g_w[n]) * fmaxf(h[(long)n * 256 + c], 0.f);
    atomicAdd(&g_z[c], local);
}

// pooled = (z @ W3)/(2N) + b3 ; out = pooled @ Wl + bl
__global__ void k_final(const float* __restrict__ W3, const float* __restrict__ b3,
                        const float* __restrict__ Wl, const float* __restrict__ bl,
                        float* __restrict__ out) {
    int j = threadIdx.x;
    __shared__ float sz[HID];
    __shared__ float so[8];
    sz[j] = g_z[j];
    if (j < 8) so[j] = 0.f;
    __syncthreads();

    float acc = 0.f;
#pragma unroll 8
    for (int k = 0; k < HID; k++)
        acc = fmaf(sz[k], W3[k * HID + j], acc);
    float pv = acc * (1.0f / (2.0f * N_NODES)) + b3[j];

#pragma unroll
    for (int c = 0; c < 5; c++)
        atomicAdd(&so[c], pv * Wl[j * 5 + c]);
    __syncthreads();
    if (j < 5) out[j] = so[j] + bl[j];
}

// ---------------------------------------------------------------------------
extern "C" void kernel_launch(void* const* d_in, const int* in_sizes, int n_in,
                              void* d_out, int out_size) {
    const float* x1 = (const float*)d_in[0];
    const int*   ei1 = (const int*)d_in[1];
    const float* x2 = (const float*)d_in[2];
    const int*   ei2 = (const int*)d_in[3];
    const float* W1 = (const float*)d_in[4];
    const float* b1 = (const float*)d_in[5];
    const float* W2 = (const float*)d_in[6];
    const float* b2 = (const float*)d_in[7];
    const float* W3 = (const float*)d_in[8];
    const float* b3 = (const float*)d_in[9];
    const float* Wl = (const float*)d_in[10];
    const float* bl = (const float*)d_in[11];
    float* out = (float*)d_out;

    float *deg, *w, *z, *B, *C;
    cudaGetSymbolAddress((void**)&deg, g_deg);
    cudaGetSymbolAddress((void**)&w,   g_w);
    cudaGetSymbolAddress((void**)&z,   g_z);
    cudaGetSymbolAddress((void**)&B,   g_bufB);
    cudaGetSymbolAddress((void**)&C,   g_bufC);

    const dim3 gemm_grid(4, (N_NODES + 127) / 128);
    const int edge_blocks = (N_EDGES + 255) / 256;
    const int node_blocks = (N_NODES + 255) / 256;

    cudaMemsetAsync(z, 0, HID * sizeof(float));

    for (int br = 0; br < 2; br++) {
        const float* x  = br == 0 ? x1 : x2;
        const int*   ei = br == 0 ? ei1 : ei2;
        const int* src = ei;
        const int* dst = ei + N_EDGES;

        // graph preprocessing (once per branch, reused by both layers)
        cudaMemsetAsync(deg, 0, N_NODES * sizeof(float));
        cudaMemsetAsync(w,   0, N_NODES * sizeof(float));
        k_deg<<<edge_blocks, 256>>>(dst);
        k_dinv<<<node_blocks, 256>>>();
        k_scan<<<1, 1024>>>();
        k_fill<<<edge_blocks, 256>>>(src, dst);
        k_wself<<<node_blocks, 256>>>();

        // layer 1
        k_gemm<false><<<gemm_grid, 256>>>(x, W1, B);
        k_gather<<<N_NODES, 256>>>(B, b1, C);

        // layer 2 (relu fused into gemm load)
        k_gemm<true><<<gemm_grid, 256>>>(C, W2, B);
        k_gather<<<N_NODES, 256>>>(B, b2, C);

        // layer 3 collapsed
        k_zred<<<256, 256>>>(C);
    }

    k_final<<<1, 256>>>(W3, b3, Wl, bl, out);
}

// round 4
// speedup vs baseline: 2.0856x; 1.1178x over previous
#include <cuda_runtime.h>
#include <mma.h>
using namespace nvcuda;

#define N_NODES 20000
#define N_EDGES 320000
#define HID 256
#define NF (N_NODES * HID)

// ---------------- scratch (device globals; no allocation allowed) ----------
__device__ float g_deg[2 * N_NODES];
__device__ float g_dinv[2 * N_NODES];
__device__ float g_w[2 * N_NODES];
__device__ float g_z[HID];
__device__ float g_bufB[2 * NF];        // xw (gemm output), both branches
__device__ float g_bufC[2 * NF];        // layer pre-relu output, both branches
__device__ int   g_rowptr[2 * (N_NODES + 1)];
__device__ int   g_cursor[2 * N_NODES];
__device__ int   g_csr_src[2 * N_EDGES];
__device__ float g_csr_coef[2 * N_EDGES];

__device__ __forceinline__ float to_tf32(float x) {
    unsigned u;
    asm("cvt.rna.tf32.f32 %0, %1;" : "=r"(u) : "f"(x));
    return __uint_as_float(u);
}

// ---------------- batched degree / dinv -------------------------------------
__global__ void k_deg(const int* __restrict__ dst0, const int* __restrict__ dst1) {
    int e = blockIdx.x * blockDim.x + threadIdx.x;
    if (e >= 2 * N_EDGES) return;
    int br = e >= N_EDGES;
    int le = e - br * N_EDGES;
    int d = br ? dst1[le] : dst0[le];
    atomicAdd(&g_deg[br * N_NODES + d], 1.0f);
}

__global__ void k_dinv() {
    int n = blockIdx.x * blockDim.x + threadIdx.x;
    if (n < 2 * N_NODES) g_dinv[n] = rsqrtf(g_deg[n] + 1.0f);
}

// ---------------- per-branch exclusive scan (one block per branch) ----------
__global__ __launch_bounds__(1024) void k_scan() {
    __shared__ int partial[1024];
    const int br = blockIdx.x;
    const int t = threadIdx.x;
    const int CH = 20;  // 1024*20 >= 20000
    int local[CH];
    int base = t * CH;
    int s = 0;
#pragma unroll
    for (int i = 0; i < CH; i++) {
        int idx = base + i;
        int d = (idx < N_NODES) ? (int)g_deg[br * N_NODES + idx] : 0;
        local[i] = s;
        s += d;
    }
    partial[t] = s;
    __syncthreads();
    for (int off = 1; off < 1024; off <<= 1) {
        int v = (t >= off) ? partial[t - off] : 0;
        __syncthreads();
        partial[t] += v;
        __syncthreads();
    }
    int offset = (t > 0) ? partial[t - 1] : 0;
#pragma unroll
    for (int i = 0; i < CH; i++) {
        int idx = base + i;
        if (idx < N_NODES) {
            int v = offset + local[i];
            g_rowptr[br * (N_NODES + 1) + idx] = v;
            g_cursor[br * N_NODES + idx] = v;
        }
    }
    if (t == 1023) g_rowptr[br * (N_NODES + 1) + N_NODES] = partial[1023];
}

// ---------------- batched CSR fill (+ w[src] accumulation) -----------------
__global__ void k_fill(const int* __restrict__ src0, const int* __restrict__ dst0,
                       const int* __restrict__ src1, const int* __restrict__ dst1) {
    int e = blockIdx.x * blockDim.x + threadIdx.x;
    if (e >= 2 * N_EDGES) return;
    int br = e >= N_EDGES;
    int le = e - br * N_EDGES;
    int s = br ? src1[le] : src0[le];
    int d = br ? dst1[le] : dst0[le];
    float coef = g_dinv[br * N_NODES + s] * g_dinv[br * N_NODES + d];
    int pos = atomicAdd(&g_cursor[br * N_NODES + d], 1);
    g_csr_src[br * N_EDGES + pos] = s;
    g_csr_coef[br * N_EDGES + pos] = coef;
    atomicAdd(&g_w[br * N_NODES + s], coef);
}

__global__ void k_wself() {
    int n = blockIdx.x * blockDim.x + threadIdx.x;
    if (n < 2 * N_NODES) {
        float di = g_dinv[n];
        g_w[n] += di * di;
    }
}

// ---------------- tf32 tensor-core GEMM: C[M,256] = act(A)[M,256] @ W -------
// BM=128, BN=64, KC=32, 8 warps. Each warp: 16 rows x 64 cols (4 wmma frags).
template <bool RELU>
__global__ __launch_bounds__(256) void k_gemm_tc(const float* __restrict__ A,
                                                 const float* __restrict__ W,
                                                 float* __restrict__ C, int M) {
    __shared__ float As[128][36];  // lda=36 (mult of 4)
    __shared__ float Bs[32][72];   // ldb=72 (mult of 4)

    const int tid = threadIdx.x;
    const int warp = tid >> 5;
    const int row0 = blockIdx.y * 128;
    const int col0 = blockIdx.x * 64;

    wmma::fragment<wmma::accumulator, 16, 16, 8, float> c[4];
#pragma unroll
    for (int j = 0; j < 4; j++) wmma::fill_fragment(c[j], 0.f);

    const int ar  = tid >> 1;           // 0..127
    const int ac0 = (tid & 1) * 16;     // 0 or 16
    const int brr = tid >> 3;           // 0..31
    const int bc0 = (tid & 7) * 8;      // 0..56

    for (int kt = 0; kt < 256; kt += 32) {
        const int gr = row0 + ar;
#pragma unroll
        for (int h = 0; h < 4; h++) {
            float4 v = make_float4(0.f, 0.f, 0.f, 0.f);
            if (gr < M)
                v = *(const float4*)(A + (long)gr * 256 + kt + ac0 + h * 4);
            if (RELU) {
                v.x = fmaxf(v.x, 0.f); v.y = fmaxf(v.y, 0.f);
                v.z = fmaxf(v.z, 0.f); v.w = fmaxf(v.w, 0.f);
            }
            float4 r = make_float4(to_tf32(v.x), to_tf32(v.y), to_tf32(v.z), to_tf32(v.w));
            *(float4*)&As[ar][ac0 + h * 4] = r;
        }
#pragma unroll
        for (int h = 0; h < 2; h++) {
            float4 v = *(const float4*)(W + (long)(kt + brr) * 256 + col0 + bc0 + h * 4);
            float4 r = make_float4(to_tf32(v.x), to_tf32(v.y), to_tf32(v.z), to_tf32(v.w));
            *(float4*)&Bs[brr][bc0 + h * 4] = r;
        }
        __syncthreads();

#pragma unroll
        for (int kk = 0; kk < 32; kk += 8) {
            wmma::fragment<wmma::matrix_a, 16, 16, 8, wmma::precision::tf32, wmma::row_major> a;
            wmma::load_matrix_sync(a, &As[warp * 16][kk], 36);
#pragma unroll
            for (int j = 0; j < 4; j++) {
                wmma::fragment<wmma::matrix_b, 16, 16, 8, wmma::precision::tf32, wmma::row_major> b;
                wmma::load_matrix_sync(b, &Bs[kk][j * 16], 72);
                wmma::mma_sync(c[j], a, b, c[j]);
            }
        }
        __syncthreads();
    }

    const int wrow = row0 + warp * 16;
    if (wrow < M) {  // M is a multiple of 16: warp tiles are all-in or all-out
#pragma unroll
        for (int j = 0; j < 4; j++)
            wmma::store_matrix_sync(C + (long)wrow * 256 + col0 + j * 16, c[j],
                                    256, wmma::mem_row_major);
    }
}

// ---------------- batched CSR gather aggregation ----------------------------
// One block per (branch,node): C[row] = sum coef*xw[src] + xw[row]*dinv^2 + b
__global__ __launch_bounds__(256) void k_gather(const float* __restrict__ xw,
                                                const float* __restrict__ bias,
                                                float* __restrict__ C) {
    const int row = blockIdx.x;              // 0..2*N_NODES-1
    const int br = row >= N_NODES;
    const int n = row - br * N_NODES;
    const int c = threadIdx.x;
    const int* rowptr = g_rowptr + br * (N_NODES + 1);
    const int beg = rowptr[n];
    const int end = rowptr[n + 1];
    const float di = g_dinv[row];
    const float* xwb = xw + (long)br * NF;
    const int* csrc = g_csr_src + br * N_EDGES;
    const float* ccoef = g_csr_coef + br * N_EDGES;

    float acc = fmaf(xwb[(long)n * 256 + c], di * di, bias[c]);

    __shared__ int   ss[256];
    __shared__ float sc[256];

    for (int chunk = beg; chunk < end; chunk += 256) {
        const int m = min(256, end - chunk);
        if (c < m) {
            ss[c] = csrc[chunk + c];
            sc[c] = ccoef[chunk + c];
        }
        __syncthreads();

        float a0 = 0.f, a1 = 0.f, a2 = 0.f, a3 = 0.f;
        int i = 0;
        for (; i + 4 <= m; i += 4) {
            a0 = fmaf(sc[i + 0], xwb[(long)ss[i + 0] * 256 + c], a0);
            a1 = fmaf(sc[i + 1], xwb[(long)ss[i + 1] * 256 + c], a1);
            a2 = fmaf(sc[i + 2], xwb[(long)ss[i + 2] * 256 + c], a2);
            a3 = fmaf(sc[i + 3], xwb[(long)ss[i + 3] * 256 + c], a3);
        }
        for (; i < m; i++)
            a0 = fmaf(sc[i], xwb[(long)ss[i] * 256 + c], a0);
        acc += (a0 + a1) + (a2 + a3);
        __syncthreads();
    }
    C[(long)row * 256 + c] = acc;
}

// z[c] = sum over both branches' rows: w[row] * relu(h[row][c])
__global__ __launch_bounds__(256) void k_zred(const float* __restrict__ h) {
    int c = threadIdx.x;
    float local = 0.f;
    for (int row = blockIdx.x; row < 2 * N_NODES; row += gridDim.x)
        local += __ldg(&g_w[row]) * fmaxf(h[(long)row * 256 + c], 0.f);
    atomicAdd(&g_z[c], local);
}

// pooled = (z @ W3)/(2N) + b3 ; out = pooled @ Wl + bl
__global__ void k_final(const float* __restrict__ W3, const float* __restrict__ b3,
                        const float* __restrict__ Wl, const float* __restrict__ bl,
                        float* __restrict__ out) {
    int j = threadIdx.x;
    __shared__ float sz[HID];
    __shared__ float so[8];
    sz[j] = g_z[j];
    if (j < 8) so[j] = 0.f;
    __syncthreads();

    float acc = 0.f;
#pragma unroll 8
    for (int k = 0; k < HID; k++)
        acc = fmaf(sz[k], W3[k * HID + j], acc);
    float pv = acc * (1.0f / (2.0f * N_NODES)) + b3[j];

#pragma unroll
    for (int c = 0; c < 5; c++)
        atomicAdd(&so[c], pv * Wl[j * 5 + c]);
    __syncthreads();
    if (j < 5) out[j] = so[j] + bl[j];
}

// ---------------------------------------------------------------------------
extern "C" void kernel_launch(void* const* d_in, const int* in_sizes, int n_in,
                              void* d_out, int out_size) {
    const float* x1 = (const float*)d_in[0];
    const int*   ei1 = (const int*)d_in[1];
    const float* x2 = (const float*)d_in[2];
    const int*   ei2 = (const int*)d_in[3];
    const float* W1 = (const float*)d_in[4];
    const float* b1 = (const float*)d_in[5];
    const float* W2 = (const float*)d_in[6];
    const float* b2 = (const float*)d_in[7];
    const float* W3 = (const float*)d_in[8];
    const float* b3 = (const float*)d_in[9];
    const float* Wl = (const float*)d_in[10];
    const float* bl = (const float*)d_in[11];
    float* out = (float*)d_out;

    float *deg, *w, *z, *B, *C;
    cudaGetSymbolAddress((void**)&deg, g_deg);
    cudaGetSymbolAddress((void**)&w,   g_w);
    cudaGetSymbolAddress((void**)&z,   g_z);
    cudaGetSymbolAddress((void**)&B,   g_bufB);
    cudaGetSymbolAddress((void**)&C,   g_bufC);

    const int* src0 = ei1;
    const int* dst0 = ei1 + N_EDGES;
    const int* src1 = ei2;
    const int* dst1 = ei2 + N_EDGES;

    const int e2_blocks = (2 * N_EDGES + 255) / 256;
    const int n2_blocks = (2 * N_NODES + 255) / 256;
    const dim3 gemm1_grid(4, (N_NODES + 127) / 128);       // 157
    const dim3 gemm2_grid(4, (2 * N_NODES + 127) / 128);   // 313

    cudaMemsetAsync(z, 0, HID * sizeof(float));
    cudaMemsetAsync(deg, 0, 2 * N_NODES * sizeof(float));
    cudaMemsetAsync(w,   0, 2 * N_NODES * sizeof(float));

    // graph preprocessing (both branches batched)
    k_deg<<<e2_blocks, 256>>>(dst0, dst1);
    k_dinv<<<n2_blocks, 256>>>();
    k_scan<<<2, 1024>>>();
    k_fill<<<e2_blocks, 256>>>(src0, dst0, src1, dst1);
    k_wself<<<n2_blocks, 256>>>();

    // layer 1: per-branch GEMM (inputs are separate buffers), batched gather
    k_gemm_tc<false><<<gemm1_grid, 256>>>(x1, W1, B,      N_NODES);
    k_gemm_tc<false><<<gemm1_grid, 256>>>(x2, W1, B + NF, N_NODES);
    k_gather<<<2 * N_NODES, 256>>>(B, b1, C);

    // layer 2: one batched GEMM over both branches (relu fused on load)
    k_gemm_tc<true><<<gemm2_grid, 256>>>(C, W2, B, 2 * N_NODES);
    k_gather<<<2 * N_NODES, 256>>>(B, b2, C);

    // layer 3 collapsed
    k_zred<<<256, 256>>>(C);
    k_final<<<1, 256>>>(W3, b3, Wl, bl, out);
}

// round 5
// speedup vs baseline: 2.3872x; 1.1446x over previous
#include <cuda_runtime.h>
#include <mma.h>
using namespace nvcuda;

#define N_NODES 20000
#define N_EDGES 320000
#define HID 256
#define NF (N_NODES * HID)

// ---------------- scratch (device globals; no allocation allowed) ----------
__device__ float g_deg[2 * N_NODES];
__device__ float g_dinv[2 * N_NODES];
__device__ float g_w[2 * N_NODES];
__device__ float g_z[HID];
__device__ float g_bufB[2 * NF];        // xw (gemm output), both branches
__device__ float g_bufC[2 * NF];        // layer output (post-relu), both branches
__device__ int   g_rowptr[2 * (N_NODES + 1)];
__device__ int   g_cursor[2 * N_NODES];
__device__ int   g_csr_src[2 * N_EDGES];
__device__ float g_csr_coef[2 * N_EDGES];

__device__ __forceinline__ float to_tf32(float x) {
    unsigned u;
    asm("cvt.rna.tf32.f32 %0, %1;" : "=r"(u) : "f"(x));
    return __uint_as_float(u);
}

// ---------------- batched degree -------------------------------------------
__global__ void k_deg(const int* __restrict__ dst0, const int* __restrict__ dst1) {
    int e = blockIdx.x * blockDim.x + threadIdx.x;
    if (e >= 2 * N_EDGES) return;
    int br = e >= N_EDGES;
    int le = e - br * N_EDGES;
    int d = br ? dst1[le] : dst0[le];
    atomicAdd(&g_deg[br * N_NODES + d], 1.0f);
}

// ---------------- per-branch scan + dinv + w-self (one block per branch) ---
__global__ __launch_bounds__(1024) void k_scan() {
    __shared__ int partial[1024];
    const int br = blockIdx.x;
    const int t = threadIdx.x;
    const int CH = 20;  // 1024*20 >= 20000
    int local[CH];
    int base = t * CH;
    int s = 0;
#pragma unroll
    for (int i = 0; i < CH; i++) {
        int idx = base + i;
        float d = (idx < N_NODES) ? g_deg[br * N_NODES + idx] : 0.f;
        local[i] = s;
        s += (int)d;
        if (idx < N_NODES) {
            float dv = rsqrtf(d + 1.0f);
            g_dinv[br * N_NODES + idx] = dv;
            g_w[br * N_NODES + idx] = dv * dv;   // self-loop weight term
        }
    }
    partial[t] = s;
    __syncthreads();
    for (int off = 1; off < 1024; off <<= 1) {
        int v = (t >= off) ? partial[t - off] : 0;
        __syncthreads();
        partial[t] += v;
        __syncthreads();
    }
    int offset = (t > 0) ? partial[t - 1] : 0;
#pragma unroll
    for (int i = 0; i < CH; i++) {
        int idx = base + i;
        if (idx < N_NODES) {
            int v = offset + local[i];
            g_rowptr[br * (N_NODES + 1) + idx] = v;
            g_cursor[br * N_NODES + idx] = v;
        }
    }
    if (t == 1023) g_rowptr[br * (N_NODES + 1) + N_NODES] = partial[1023];
}

// ---------------- batched CSR fill (+ w[src] accumulation) -----------------
__global__ void k_fill(const int* __restrict__ src0, const int* __restrict__ dst0,
                       const int* __restrict__ src1, const int* __restrict__ dst1) {
    int e = blockIdx.x * blockDim.x + threadIdx.x;
    if (e >= 2 * N_EDGES) return;
    int br = e >= N_EDGES;
    int le = e - br * N_EDGES;
    int s = br ? src1[le] : src0[le];
    int d = br ? dst1[le] : dst0[le];
    float coef = g_dinv[br * N_NODES + s] * g_dinv[br * N_NODES + d];
    int pos = atomicAdd(&g_cursor[br * N_NODES + d], 1);
    g_csr_src[pos + br * N_EDGES] = s;
    g_csr_coef[pos + br * N_EDGES] = coef;
    atomicAdd(&g_w[br * N_NODES + s], coef);
}

// ---------------- tf32 tensor-core GEMM, 128x128 tile, pipelined ----------
// Out[M,256] = A[M,256] @ W[256,256].  blockIdx.z selects (A0,A1) and output
// half (for batching the two layer-1 branch GEMMs into one launch).
__global__ __launch_bounds__(256) void k_gemm_tc(const float* __restrict__ A0,
                                                 const float* __restrict__ A1,
                                                 const float* __restrict__ Wm,
                                                 float* __restrict__ Out, int M) {
    __shared__ float As[128][20];   // [row][k], pad to 20 (mult of 4)
    __shared__ float Bs[16][132];   // [k][col], pad to 132 (mult of 4)

    const float* A = blockIdx.z ? A1 : A0;
    float* C = Out + (long)blockIdx.z * M * 256;

    const int tid = threadIdx.x;
    const int warp = tid >> 5;
    const int row0 = blockIdx.y * 128;
    const int col0 = blockIdx.x * 128;

    wmma::fragment<wmma::accumulator, 16, 16, 8, float> c[8];
#pragma unroll
    for (int j = 0; j < 8; j++) wmma::fill_fragment(c[j], 0.f);

    const int ar = tid >> 1;          // 0..127
    const int ac = (tid & 1) * 8;     // 0 or 8
    const int brw = tid >> 4;         // 0..15
    const int bc = (tid & 15) * 8;    // 0..120
    const int gr = row0 + ar;

    float4 a0v, a1v, b0v, b1v;
    // prefetch k-chunk 0
    if (gr < M) {
        a0v = *(const float4*)(A + (long)gr * 256 + ac);
        a1v = *(const float4*)(A + (long)gr * 256 + ac + 4);
    } else {
        a0v = make_float4(0.f, 0.f, 0.f, 0.f);
        a1v = a0v;
    }
    b0v = *(const float4*)(Wm + (long)brw * 256 + col0 + bc);
    b1v = *(const float4*)(Wm + (long)brw * 256 + col0 + bc + 4);

    for (int kt = 0; kt < 256; kt += 16) {
        // stage current chunk into smem (tf32-rounded)
        As[ar][ac + 0] = to_tf32(a0v.x); As[ar][ac + 1] = to_tf32(a0v.y);
        As[ar][ac + 2] = to_tf32(a0v.z); As[ar][ac + 3] = to_tf32(a0v.w);
        As[ar][ac + 4] = to_tf32(a1v.x); As[ar][ac + 5] = to_tf32(a1v.y);
        As[ar][ac + 6] = to_tf32(a1v.z); As[ar][ac + 7] = to_tf32(a1v.w);
        Bs[brw][bc + 0] = to_tf32(b0v.x); Bs[brw][bc + 1] = to_tf32(b0v.y);
        Bs[brw][bc + 2] = to_tf32(b0v.z); Bs[brw][bc + 3] = to_tf32(b0v.w);
        Bs[brw][bc + 4] = to_tf32(b1v.x); Bs[brw][bc + 5] = to_tf32(b1v.y);
        Bs[brw][bc + 6] = to_tf32(b1v.z); Bs[brw][bc + 7] = to_tf32(b1v.w);
        __syncthreads();

        // prefetch next chunk (overlaps with mma below)
        if (kt + 16 < 256) {
            const int kn = kt + 16;
            if (gr < M) {
                a0v = *(const float4*)(A + (long)gr * 256 + kn + ac);
                a1v = *(const float4*)(A + (long)gr * 256 + kn + ac + 4);
            }
            b0v = *(const float4*)(Wm + (long)(kn + brw) * 256 + col0 + bc);
            b1v = *(const float4*)(Wm + (long)(kn + brw) * 256 + col0 + bc + 4);
        }

#pragma unroll
        for (int kk = 0; kk < 16; kk += 8) {
            wmma::fragment<wmma::matrix_a, 16, 16, 8, wmma::precision::tf32, wmma::row_major> a;
            wmma::load_matrix_sync(a, &As[warp * 16][kk], 20);
#pragma unroll
            for (int j = 0; j < 8; j++) {
                wmma::fragment<wmma::matrix_b, 16, 16, 8, wmma::precision::tf32, wmma::row_major> b;
                wmma::load_matrix_sync(b, &Bs[kk][j * 16], 132);
                wmma::mma_sync(c[j], a, b, c[j]);
            }
        }
        __syncthreads();
    }

    const int wrow = row0 + warp * 16;
    if (wrow < M) {  // M multiple of 16: warp tiles all-in or all-out
#pragma unroll
        for (int j = 0; j < 8; j++)
            wmma::store_matrix_sync(C + (long)wrow * 256 + col0 + j * 16, c[j],
                                    256, wmma::mem_row_major);
    }
}

// ---------------- batched CSR gather, float4 lanes, sync-free --------------
// 4 nodes per block, 64 threads each. C[row] = relu(sum coef*xw[src] + self + b)
__global__ __launch_bounds__(256) void k_gather(const float* __restrict__ xw,
                                                const float* __restrict__ bias,
                                                float* __restrict__ C) {
    const int g = threadIdx.x >> 6;
    const int t = threadIdx.x & 63;
    const int row = blockIdx.x * 4 + g;          // grid*4 == 2*N_NODES exactly
    const int br = row >= N_NODES;
    const int n = row - br * N_NODES;
    const int* rowptr = g_rowptr + br * (N_NODES + 1);
    const int beg = rowptr[n];
    const int end = rowptr[n + 1];
    const float di = g_dinv[row];
    const float* xwb = xw + (long)br * NF;
    const int* csrc = g_csr_src + br * N_EDGES;
    const float* ccoef = g_csr_coef + br * N_EDGES;

    const float dd = di * di;
    float4 bs = *(const float4*)(bias + t * 4);
    float4 sf = *(const float4*)(xwb + (long)n * 256 + t * 4);
    float4 acc0, acc1, acc2, acc3;
    acc0.x = fmaf(sf.x, dd, bs.x); acc0.y = fmaf(sf.y, dd, bs.y);
    acc0.z = fmaf(sf.z, dd, bs.z); acc0.w = fmaf(sf.w, dd, bs.w);
    acc1 = make_float4(0.f, 0.f, 0.f, 0.f);
    acc2 = acc1; acc3 = acc1;

    int i = beg;
    for (; i + 4 <= end; i += 4) {
        int s0 = csrc[i], s1 = csrc[i + 1], s2 = csrc[i + 2], s3 = csrc[i + 3];
        float c0 = ccoef[i], c1 = ccoef[i + 1], c2 = ccoef[i + 2], c3 = ccoef[i + 3];
        float4 v0 = *(const float4*)(xwb + (long)s0 * 256 + t * 4);
        float4 v1 = *(const float4*)(xwb + (long)s1 * 256 + t * 4);
        float4 v2 = *(const float4*)(xwb + (long)s2 * 256 + t * 4);
        float4 v3 = *(const float4*)(xwb + (long)s3 * 256 + t * 4);
        acc0.x = fmaf(c0, v0.x, acc0.x); acc0.y = fmaf(c0, v0.y, acc0.y);
        acc0.z = fmaf(c0, v0.z, acc0.z); acc0.w = fmaf(c0, v0.w, acc0.w);
        acc1.x = fmaf(c1, v1.x, acc1.x); acc1.y = fmaf(c1, v1.y, acc1.y);
        acc1.z = fmaf(c1, v1.z, acc1.z); acc1.w = fmaf(c1, v1.w, acc1.w);
        acc2.x = fmaf(c2, v2.x, acc2.x); acc2.y = fmaf(c2, v2.y, acc2.y);
        acc2.z = fmaf(c2, v2.z, acc2.z); acc2.w = fmaf(c2, v2.w, acc2.w);
        acc3.x = fmaf(c3, v3.x, acc3.x); acc3.y = fmaf(c3, v3.y, acc3.y);
        acc3.z = fmaf(c3, v3.z, acc3.z); acc3.w = fmaf(c3, v3.w, acc3.w);
    }
    for (; i < end; i++) {
        int s = csrc[i];
        float cc = ccoef[i];
        float4 v = *(const float4*)(xwb + (long)s * 256 + t * 4);
        acc0.x = fmaf(cc, v.x, acc0.x); acc0.y = fmaf(cc, v.y, acc0.y);
        acc0.z = fmaf(cc, v.z, acc0.z); acc0.w = fmaf(cc, v.w, acc0.w);
    }
    float4 o;
    o.x = fmaxf(acc0.x + acc1.x + acc2.x + acc3.x, 0.f);
    o.y = fmaxf(acc0.y + acc1.y + acc2.y + acc3.y, 0.f);
    o.z = fmaxf(acc0.z + acc1.z + acc2.z + acc3.z, 0.f);
    o.w = fmaxf(acc0.w + acc1.w + acc2.w + acc3.w, 0.f);
    *(float4*)(C + (long)row * 256 + t * 4) = o;
}

// z[c] = sum over rows: w[row] * h[row][c]   (h already relu'd by gather)
__global__ __launch_bounds__(256) void k_zred(const float* __restrict__ h) {
    int c = threadIdx.x;
    float local = 0.f;
    for (int row = blockIdx.x; row < 2 * N_NODES; row += gridDim.x)
        local += __ldg(&g_w[row]) * h[(long)row * 256 + c];
    atomicAdd(&g_z[c], local);
}

// pooled = (z @ W3)/(2N) + b3 ; out = pooled @ Wl + bl
__global__ void k_final(const float* __restrict__ W3, const float* __restrict__ b3,
                        const float* __restrict__ Wl, const float* __restrict__ bl,
                        float* __restrict__ out) {
    int j = threadIdx.x;
    __shared__ float sz[HID];
    __shared__ float so[8];
    sz[j] = g_z[j];
    if (j < 8) so[j] = 0.f;
    __syncthreads();

    float acc = 0.f;
#pragma unroll 8
    for (int k = 0; k < HID; k++)
        acc = fmaf(sz[k], W3[k * HID + j], acc);
    float pv = acc * (1.0f / (2.0f * N_NODES)) + b3[j];

#pragma unroll
    for (int c = 0; c < 5; c++)
        atomicAdd(&so[c], pv * Wl[j * 5 + c]);
    __syncthreads();
    if (j < 5) out[j] = so[j] + bl[j];
}

// ---------------------------------------------------------------------------
extern "C" void kernel_launch(void* const* d_in, const int* in_sizes, int n_in,
                              void* d_out, int out_size) {
    const float* x1 = (const float*)d_in[0];
    const int*   ei1 = (const int*)d_in[1];
    const float* x2 = (const float*)d_in[2];
    const int*   ei2 = (const int*)d_in[3];
    const float* W1 = (const float*)d_in[4];
    const float* b1 = (const float*)d_in[5];
    const float* W2 = (const float*)d_in[6];
    const float* b2 = (const float*)d_in[7];
    const float* W3 = (const float*)d_in[8];
    const float* b3 = (const float*)d_in[9];
    const float* Wl = (const float*)d_in[10];
    const float* bl = (const float*)d_in[11];
    float* out = (float*)d_out;

    float *deg, *z, *B, *C;
    cudaGetSymbolAddress((void**)&deg, g_deg);
    cudaGetSymbolAddress((void**)&z,   g_z);
    cudaGetSymbolAddress((void**)&B,   g_bufB);
    cudaGetSymbolAddress((void**)&C,   g_bufC);

    const int* src0 = ei1;
    const int* dst0 = ei1 + N_EDGES;
    const int* src1 = ei2;
    const int* dst1 = ei2 + N_EDGES;

    const int e2_blocks = (2 * N_EDGES + 255) / 256;
    const dim3 gemm1_grid(2, (N_NODES + 127) / 128, 2);       // 157 row blocks x 2 branches
    const dim3 gemm2_grid(2, (2 * N_NODES + 127) / 128, 1);   // 313 row blocks

    cudaMemsetAsync(z, 0, HID * sizeof(float));
    cudaMemsetAsync(deg, 0, 2 * N_NODES * sizeof(float));

    // graph preprocessing (both branches batched)
    k_deg<<<e2_blocks, 256>>>(dst0, dst1);
    k_scan<<<2, 1024>>>();                 // rowptr + dinv + w-self fused
    k_fill<<<e2_blocks, 256>>>(src0, dst0, src1, dst1);

    // layer 1: both branch GEMMs in one launch, batched gather (writes relu)
    k_gemm_tc<<<gemm1_grid, 256>>>(x1, x2, W1, B, N_NODES);
    k_gather<<<(2 * N_NODES) / 4, 256>>>(B, b1, C);

    // layer 2: one batched GEMM over both branches
    k_gemm_tc<<<gemm2_grid, 256>>>(C, C, W2, B, 2 * N_NODES);
    k_gather<<<(2 * N_NODES) / 4, 256>>>(B, b2, C);

    // layer 3 collapsed
    k_zred<<<256, 256>>>(C);
    k_final<<<1, 256>>>(W3, b3, Wl, bl, out);
}